// round 10
// baseline (speedup 1.0000x reference)
#include <cuda_runtime.h>
#include <cuda_bf16.h>

#define NNN     16384
#define MODIN   113
#define MODOUT  57

typedef unsigned long long u64;

#define OUT_H    16384
#define OUT_MSG  (OUT_H + 4194304)
#define OUT_HEB  (OUT_MSG + 4194304)

// per (b,n) scratch row of 64: [0:25) sigmoids (16 conn, 8 border, decay@24), [25:57) prim_new
__device__ float g_scr[(size_t)8 * NNN * 64];

__device__ __forceinline__ u64 pk2(float w) {
    u64 r; asm("mov.b64 %0, {%1, %1};" : "=l"(r) : "f"(w)); return r;
}
__device__ __forceinline__ void fma2(u64 &a, u64 b, u64 c) {
    asm("fma.rn.f32x2 %0, %1, %2, %0;" : "+l"(a) : "l"(b), "l"(c));
}
__device__ __forceinline__ void upk2(u64 v, float &lo, float &hi) {
    asm("mov.b64 {%0,%1}, %2;" : "=f"(lo), "=f"(hi) : "l"(v));
}
__device__ __forceinline__ float mytanh(float x) {
    float e = __expf(2.0f * x);
    return 1.0f - __fdividef(2.0f, e + 1.0f);
}
__device__ __forceinline__ float sigm(float x) {
    return __fdividef(1.0f, 1.0f + __expf(-x));
}
__device__ __forceinline__ unsigned smem_u32(const void* p) {
    return (unsigned)__cvta_generic_to_shared(p);
}
__device__ __forceinline__ void cpasync16(unsigned saddr, const void* g) {
    asm volatile("cp.async.cg.shared.global [%0], [%1], 16;" :: "r"(saddr), "l"(g));
}
__device__ __forceinline__ void cp_commit() {
    asm volatile("cp.async.commit_group;");
}
template<int N> __device__ __forceinline__ void cp_wait() {
    asm volatile("cp.async.wait_group %0;" :: "n"(N));
}

// psum-writing partial GEMV; x via LDS.128 broadcast (R7 psum layout)
__device__ __forceinline__ void gemv_part(const float* __restrict__ W, int iStride,
                                          const float* __restrict__ X,
                                          float* __restrict__ ps,
                                          int kbeg, int kend)
{
    u64 a0 = 0, a1 = 0, a2 = 0, a3 = 0;
    const float* w = W + kbeg * iStride;
    const ulonglong2* x = (const ulonglong2*)(X + kbeg * 8);
#pragma unroll 4
    for (int i = kbeg; i < kend; ++i) {
        u64 wp = pk2(*w); w += iStride;
        ulonglong2 v0 = x[0], v1 = x[1]; x += 2;
        fma2(a0, wp, v0.x); fma2(a1, wp, v0.y);
        fma2(a2, wp, v1.x); fma2(a3, wp, v1.y);
    }
    u64* pp = (u64*)ps;
    pp[0] = a0; pp[1] = a1; pp[2] = a2; pp[3] = a3;
}

// dual-neuron GEMV, lane owns TWO output rows per neuron (shared weight loads)
// A[0..3]=n0 row0, A[4..7]=n0 row1, A[8..11]=n1 row0, A[12..15]=n1 row1
__device__ __forceinline__ void gemv2x2(const float* __restrict__ W0,
                                        const float* __restrict__ W1,
                                        const float* __restrict__ X0,
                                        const float* __restrict__ X1,
                                        int K, u64* A)
{
    u64 a[16];
#pragma unroll
    for (int j = 0; j < 16; j++) a[j] = 0;
    const ulonglong2* x0 = (const ulonglong2*)X0;
    const ulonglong2* x1 = (const ulonglong2*)X1;
#pragma unroll 2
    for (int i = 0; i < K; ++i) {
        u64 p0 = pk2(W0[i]), p1 = pk2(W1[i]);
        ulonglong2 u0 = x0[0], u1 = x0[1]; x0 += 2;
        ulonglong2 v0 = x1[0], v1 = x1[1]; x1 += 2;
        fma2(a[0],  p0, u0.x); fma2(a[1],  p0, u0.y);
        fma2(a[2],  p0, u1.x); fma2(a[3],  p0, u1.y);
        fma2(a[4],  p1, u0.x); fma2(a[5],  p1, u0.y);
        fma2(a[6],  p1, u1.x); fma2(a[7],  p1, u1.y);
        fma2(a[8],  p0, v0.x); fma2(a[9],  p0, v0.y);
        fma2(a[10], p0, v1.x); fma2(a[11], p0, v1.y);
        fma2(a[12], p1, v0.x); fma2(a[13], p1, v0.y);
        fma2(a[14], p1, v1.x); fma2(a[15], p1, v1.y);
    }
#pragma unroll
    for (int j = 0; j < 16; j++) A[j] = a[j];
}

// dual-neuron GEMV, lane owns ONE output row per neuron
// A[0..3]=n0, A[4..7]=n1
__device__ __forceinline__ void gemv1x2(const float* __restrict__ W,
                                        const float* __restrict__ X0,
                                        const float* __restrict__ X1,
                                        int K, u64* A)
{
    u64 a[8];
#pragma unroll
    for (int j = 0; j < 8; j++) a[j] = 0;
    const ulonglong2* x0 = (const ulonglong2*)X0;
    const ulonglong2* x1 = (const ulonglong2*)X1;
#pragma unroll 4
    for (int i = 0; i < K; ++i) {
        u64 wp = pk2(W[i]);
        ulonglong2 u0 = x0[0], u1 = x0[1]; x0 += 2;
        ulonglong2 v0 = x1[0], v1 = x1[1]; x1 += 2;
        fma2(a[0], wp, u0.x); fma2(a[1], wp, u0.y);
        fma2(a[2], wp, u1.x); fma2(a[3], wp, u1.y);
        fma2(a[4], wp, v0.x); fma2(a[5], wp, v0.y);
        fma2(a[6], wp, v1.x); fma2(a[7], wp, v1.y);
    }
#pragma unroll
    for (int j = 0; j < 8; j++) A[j] = a[j];
}

// tanh(bias + acc) for 8 packed values -> 2 float4 stores
__device__ __forceinline__ void act_store(float* dst, const u64* A, float bias)
{
    float lo, hi; float4 f0, f1;
    upk2(A[0], lo, hi); f0.x = mytanh(bias + lo); f0.y = mytanh(bias + hi);
    upk2(A[1], lo, hi); f0.z = mytanh(bias + lo); f0.w = mytanh(bias + hi);
    upk2(A[2], lo, hi); f1.x = mytanh(bias + lo); f1.y = mytanh(bias + hi);
    upk2(A[3], lo, hi); f1.z = mytanh(bias + lo); f1.w = mytanh(bias + hi);
    ((float4*)dst)[0] = f0; ((float4*)dst)[1] = f1;
}

// =================== K1: per-neuron modulator MLP (exact R7 version) ===================
#define K1_W1  0        // 32 x 113 = 3616
#define K1_W2  3616     // 32 x 57 ([h][o]) = 1824
#define K1_X   5440     // 113 x 8 batch-major = 904
#define K1_H   6344     // 32 x 8 = 256
#define K1_PS  6600     // 8 x 32 x 8 = 2048
#define K1_TOT 8648     // 34592 B

__global__ void __launch_bounds__(256, 5)
modk(const float* __restrict__ hin,  const float* __restrict__ dlog,
     const float* __restrict__ prim, const float* __restrict__ trc,
     const float* __restrict__ modw1, const float* __restrict__ modb1g,
     const float* __restrict__ modw2, const float* __restrict__ modb2g,
     const float* __restrict__ nidg)
{
    __shared__ float s[K1_TOT];
    const int tid = threadIdx.x, wid = tid >> 5, lane = tid & 31;
    const int n = blockIdx.x;

    // ---- cp.async weight staging: group0 = W1, group1 = W2 ----
    {
        unsigned sW1 = smem_u32(s + K1_W1);
        const float4* g1 = (const float4*)(modw1 + (size_t)n * (32*MODIN));
        for (int i = tid; i < 904; i += 256)
            cpasync16(sW1 + i*16, g1 + i);
        cp_commit();
        unsigned sW2 = smem_u32(s + K1_W2);
        const float4* g2 = (const float4*)(modw2 + (size_t)n * (32*MODOUT));
        for (int i = tid; i < 456; i += 256)
            cpasync16(sW2 + i*16, g2 + i);
        cp_commit();
    }

    // ---- build X (warp = batch, lane = d) ----
    {
        int b = wid;
        size_t nb = (size_t)b * NNN + n;
        s[K1_X + (16+lane)*8 + b] = hin[nb*32 + lane];
        s[K1_X + (49+lane)*8 + b] = prim[nb*32 + lane];
        s[K1_X + (81+lane)*8 + b] = nidg[(size_t)n*32 + lane];
        if (lane < 16) s[K1_X + lane*8 + b] = trc[nb*16 + lane];
        if (lane == 0) s[K1_X + 48*8 + b] = dlog[nb];
    }
    cp_wait<1>();          // W1 landed (W2 may still be in flight)
    __syncthreads();

    // ---- layer1: O=32 (lane), K=113 split over 8 warps ----
    {
        int kb = (113*wid) >> 3, ke = (113*(wid+1)) >> 3;
        gemv_part(s + K1_W1 + lane*MODIN, 1, s + K1_X,
                  s + K1_PS + (wid*32 + lane)*8, kb, ke);
    }
    __syncthreads();
    {
        int o = tid >> 3;
        float t = modb1g[n*32 + o];
#pragma unroll
        for (int w = 0; w < 8; w++) t += s[K1_PS + w*256 + tid];
        s[K1_H + tid] = mytanh(t);
    }
    cp_wait<0>();          // W2 landed
    __syncthreads();

    // ---- layer2: O=57, K=32; warp = (oh = wid&1, kseg = wid>>1) ----
    {
        int oh = wid & 1, kseg = wid >> 1;
        int o = oh*32 + lane;
        if (oh == 0 || lane < 25)
            gemv_part(s + K1_W2 + o, MODOUT, s + K1_H,
                      s + K1_PS + (wid*32 + lane)*8, kseg*8, kseg*8 + 8);
    }
    __syncthreads();

    // ---- reduce + postprocess + write scratch ----
    for (int v = tid; v < 456; v += 256) {
        int o = v >> 3, b = v & 7;
        int oh = o >> 5, ol = o & 31;
        float t = modb2g[n*57 + o];
#pragma unroll
        for (int ks = 0; ks < 4; ks++)
            t += s[K1_PS + (oh + 2*ks)*256 + ol*8 + b];
        float val = (o < 25) ? sigm(t) : (t + s[K1_X + (49 + (o-25))*8 + b]);
        g_scr[((size_t)b*NNN + n)*64 + o] = val;
    }
}

// =================== K2: 2-neurons-per-warp gather + state/msg MLPs ===================
#define OFF_SW1   0        // 64 x 97
#define OFF_SW2   6208     // 32 x 65 pad
#define OFF_MW1   8288     // 64 x 97 (96 used)
#define OFF_MW2   14496    // 32 x 65 pad
#define OFF_SB1   16576
#define OFF_SB2   16640
#define OFF_MB1   16672
#define OFF_MB2   16736
#define WS_BASE   16768
// per-warp workspace (floats): X0 97x8 | X1 97x8 | SH0 64x8 | SH1 64x8 | SG0 25x8 | SG1 25x8 | IDX 48i
#define W_X1    776
#define W_SH0   1552
#define W_SH1   2064
#define W_SG0   2576
#define W_SG1   2776
#define W_IDX   2976     // int offsets within ws: n0 conn[0:16) bord[16:24); n1 at +24
#define WSN     3024
#define K2_WARPS 13
#define K2_THREADS (K2_WARPS*32)
#define K2_FLOATS (WS_BASE + K2_WARPS*WSN)
#define K2_BYTES  (K2_FLOATS*4)
#define GRID_K2 148
#define TOT_WARPS (GRID_K2*K2_WARPS)
#define NPAIRS (NNN/2)

__global__ void __launch_bounds__(K2_THREADS, 1)
cellK2(const float* __restrict__ ccs, const float* __restrict__ hin,
       const float* __restrict__ pm,
       const float* __restrict__ sw1g, const float* __restrict__ sb1g,
       const float* __restrict__ sw2g, const float* __restrict__ sb2g,
       const float* __restrict__ mw1g, const float* __restrict__ mb1g,
       const float* __restrict__ mw2g, const float* __restrict__ mb2g,
       const float* __restrict__ nidg,
       const int*   __restrict__ conn, const int* __restrict__ bconn,
       float* __restrict__ outp)
{
    extern __shared__ float smf[];
    const int tid  = threadIdx.x;
    const int wid  = tid >> 5;
    const int lane = tid & 31;

    // ---- one-time staging of shared MLP weights ----
    for (int i = tid; i < 1552; i += K2_THREADS)
        ((float4*)(smf + OFF_SW1))[i] = ((const float4*)sw1g)[i];
    for (int i = tid; i < 2048; i += K2_THREADS) {
        int d = i >> 6, h2 = i & 63;
        smf[OFF_SW2 + d*65 + h2] = sw2g[i];
        smf[OFF_MW2 + d*65 + h2] = mw2g[i];
    }
    for (int i = tid; i < 6144; i += K2_THREADS) {
        int hh = i / 96, ii = i - hh*96;
        smf[OFF_MW1 + hh*97 + ii] = mw1g[i];
    }
    if (tid < 64) smf[OFF_SB1 + tid] = sb1g[tid];
    if (tid < 32) smf[OFF_SB2 + tid] = sb2g[tid];
    if (tid >= 64 && tid < 128) smf[OFF_MB1 + tid - 64] = mb1g[tid - 64];
    if (tid >= 32 && tid < 64) smf[OFF_MB2 + tid - 32] = mb2g[tid - 32];
    __syncthreads();

    float* ws  = smf + WS_BASE + wid*WSN;
    int*   wi  = (int*)ws;
    const int gwarp = blockIdx.x*K2_WARPS + wid;

    for (int p = gwarp; p < NPAIRS; p += TOT_WARPS) {
        const int n0 = 2*p;
        const int nc = n0 >> 8, c0 = n0 & 255;

        // ---- P0: loads for both neurons ----
#pragma unroll
        for (int nn = 0; nn < 2; nn++) {
            const int n = n0 + nn, c = c0 + nn;
            const bool isb = (c >= 4 && c < 20);
            float* X  = ws + nn*W_X1;
            float* SG = ws + W_SG0 + nn*200;
            if (lane < 16) wi[W_IDX + nn*24 + lane] = conn[n*16 + lane];
            if (isb && lane < 8)
                wi[W_IDX + nn*24 + 16 + lane] = bconn[(nc*16 + (c-4))*8 + lane];
#pragma unroll
            for (int b = 0; b < 8; b++) {
                size_t nb = (size_t)b * NNN + n;
                const float* sc = g_scr + nb*64;
                X[lane*8 + b]      = hin[nb*32 + lane];
                X[(64+lane)*8 + b] = sc[25 + lane];
                if (lane < 25) {
                    float sv = sc[lane];
                    SG[lane*8 + b] = sv;
                    if (lane == 24) X[96*8 + b] = sv;
                }
            }
        }
        __syncwarp();

        // ---- P1: gather -> X rows 32-63 (recv), both neurons ----
#pragma unroll
        for (int nn = 0; nn < 2; nn++) {
            const int n = n0 + nn, c = c0 + nn;
            const bool isb = (c >= 4 && c < 20);
            float* X  = ws + nn*W_X1;
            float* SG = ws + W_SG0 + nn*200;
            const int* ix = wi + W_IDX + nn*24;
#pragma unroll
            for (int b = 0; b < 8; b++) {
                size_t bb = (size_t)b * NNN;
                float acc = (c < 4) ? ccs[b*2048 + nc*32 + lane] : 0.0f;
#pragma unroll
                for (int k = 0; k < 16; k++) {
                    int ci = ix[k];
                    acc = fmaf(pm[(bb + nc*256 + ci)*32 + lane], SG[k*8 + b], acc);
                }
                if (isb) {
#pragma unroll
                    for (int k = 0; k < 8; k++) {
                        int bi = ix[16 + k];
                        acc = fmaf(pm[(bb + (bi>>4)*256 + 4 + (bi&15))*32 + lane],
                                   SG[(16+k)*8 + b], acc);
                    }
                }
                X[(32+lane)*8 + b] = acc;
            }
        }
        __syncwarp();

        // ---- P2: state l1 O=64 K=97, both neurons, shared weight loads ----
        {
            u64 A[16];
            gemv2x2(smf + OFF_SW1 + lane*97, smf + OFF_SW1 + (lane+32)*97,
                    ws, ws + W_X1, 97, A);
            float b0 = smf[OFF_SB1 + lane], b1 = smf[OFF_SB1 + lane + 32];
            act_store(ws + W_SH0 + lane*8,      A,      b0);
            act_store(ws + W_SH0 + (lane+32)*8, A + 4,  b1);
            act_store(ws + W_SH1 + lane*8,      A + 8,  b0);
            act_store(ws + W_SH1 + (lane+32)*8, A + 12, b1);
        }
        __syncwarp();

        // ---- P3: state l2 O=32 K=64, h_new in place; nid into rows 64-95 ----
        {
            u64 B[8];
            gemv1x2(smf + OFF_SW2 + lane*65, ws + W_SH0, ws + W_SH1, 64, B);
            float sb = smf[OFF_SB2 + lane];
#pragma unroll
            for (int nn = 0; nn < 2; nn++) {
                const int n = n0 + nn;
                float* X = ws + nn*W_X1;
                float dh[8];
                upk2(B[nn*4+0], dh[0], dh[1]); upk2(B[nn*4+1], dh[2], dh[3]);
                upk2(B[nn*4+2], dh[4], dh[5]); upk2(B[nn*4+3], dh[6], dh[7]);
#pragma unroll
                for (int b = 0; b < 8; b++) {
                    float dec = X[96*8 + b];
                    float hv  = X[lane*8 + b];
                    float hn  = dec*hv + (1.0f - dec)*mytanh(dh[b] + sb);
                    X[lane*8 + b] = hn;
                    outp[OUT_H + ((size_t)b*NNN + n)*32 + lane] = hn;
                }
                float nidv = nidg[(size_t)n*32 + lane];
                float4 nf = make_float4(nidv, nidv, nidv, nidv);
                ((float4*)(X + (64+lane)*8))[0] = nf;
                ((float4*)(X + (64+lane)*8))[1] = nf;
            }
        }
        __syncwarp();

        // ---- P4: msg l1 O=64 K=96 (X rows: h_new | recv | nid) ----
        {
            u64 A[16];
            gemv2x2(smf + OFF_MW1 + lane*97, smf + OFF_MW1 + (lane+32)*97,
                    ws, ws + W_X1, 96, A);
            float b0 = smf[OFF_MB1 + lane], b1 = smf[OFF_MB1 + lane + 32];
            act_store(ws + W_SH0 + lane*8,      A,      b0);
            act_store(ws + W_SH0 + (lane+32)*8, A + 4,  b1);
            act_store(ws + W_SH1 + lane*8,      A + 8,  b0);
            act_store(ws + W_SH1 + (lane+32)*8, A + 12, b1);
        }
        __syncwarp();

        // ---- P5: msg l2 O=32 K=64 -> STG msg, both neurons ----
        {
            u64 B[8];
            gemv1x2(smf + OFF_MW2 + lane*65, ws + W_SH0, ws + W_SH1, 64, B);
            float mb = smf[OFF_MB2 + lane];
#pragma unroll
            for (int nn = 0; nn < 2; nn++) {
                const int n = n0 + nn;
                float dm[8];
                upk2(B[nn*4+0], dm[0], dm[1]); upk2(B[nn*4+1], dm[2], dm[3]);
                upk2(B[nn*4+2], dm[4], dm[5]); upk2(B[nn*4+3], dm[6], dm[7]);
#pragma unroll
                for (int b = 0; b < 8; b++)
                    outp[OUT_MSG + ((size_t)b*NNN + n)*32 + lane] = mytanh(dm[b] + mb);
            }
        }
        __syncwarp();
    }
}

// ---------------- kernel B: hebbian + readout (2 threads per neuron) ----------------
#define SMEMB_BYTES (8448*4 + 4096*4)

__global__ void __launch_bounds__(512, 2)
cellB_kernel(const int* __restrict__ conn,
             const float* __restrict__ trc,
             float* __restrict__ outp)
{
    extern __shared__ float smb[];
    float* ms = smb;                    // 256 x 33
    int*   cs = (int*)(smb + 8448);     // 4096
    const int b  = blockIdx.x >> 6;
    const int nc = blockIdx.x & 63;
    const int tid = threadIdx.x;

    const float* msgg = outp + OUT_MSG + ((size_t)b*NNN + nc*256) * 32;
    for (int i = tid; i < 8192; i += 512)
        ms[(i >> 5)*33 + (i & 31)] = msgg[i];
    const int4* cg = (const int4*)(conn + nc*4096);
    for (int i = tid; i < 1024; i += 512) ((int4*)cs)[i] = cg[i];
    __syncthreads();

    const int c  = tid >> 1;
    const int kh = tid & 1;
    float me[32];
#pragma unroll
    for (int d = 0; d < 32; d++) me[d] = ms[c*33 + d];

    const size_t base = (size_t)b*NNN + nc*256 + c;
    float4 t4[2];
    t4[0] = ((const float4*)(trc + base*16 + kh*8))[0];
    t4[1] = ((const float4*)(trc + base*16 + kh*8))[1];

    float heb[8];
#pragma unroll
    for (int k = 0; k < 8; k++) {
        int ci = cs[c*16 + kh*8 + k];
        const float* nb = &ms[ci*33];
        float a0 = 0.0f, a1 = 0.0f;
#pragma unroll
        for (int d = 0; d < 32; d += 2) {
            a0 = fmaf(me[d],   nb[d],   a0);
            a1 = fmaf(me[d+1], nb[d+1], a1);
        }
        heb[k] = (a0 + a1) * 0.003125f;
    }
    float4* h4 = (float4*)(outp + OUT_HEB + base*16 + kh*8);
    h4[0] = make_float4(fmaf(0.9f,t4[0].x,heb[0]), fmaf(0.9f,t4[0].y,heb[1]),
                        fmaf(0.9f,t4[0].z,heb[2]), fmaf(0.9f,t4[0].w,heb[3]));
    h4[1] = make_float4(fmaf(0.9f,t4[1].x,heb[4]), fmaf(0.9f,t4[1].y,heb[5]),
                        fmaf(0.9f,t4[1].z,heb[6]), fmaf(0.9f,t4[1].w,heb[7]));

    if (tid < 32) {
        float r = 0.25f * (ms[252*33 + tid] + ms[253*33 + tid] +
                           ms[254*33 + tid] + ms[255*33 + tid]);
        outp[b*2048 + nc*32 + tid] = r;
    }
}

extern "C" void kernel_launch(void* const* d_in, const int* in_sizes, int n_in,
                              void* d_out, int out_size)
{
    const float* ccs   = (const float*)d_in[0];
    const float* hin   = (const float*)d_in[1];
    const float* pm    = (const float*)d_in[2];
    const float* dlog  = (const float*)d_in[3];
    const float* prim  = (const float*)d_in[4];
    const float* trc   = (const float*)d_in[5];
    const float* sw1   = (const float*)d_in[6];
    const float* sb1   = (const float*)d_in[7];
    const float* sw2   = (const float*)d_in[8];
    const float* sb2   = (const float*)d_in[9];
    const float* mw1   = (const float*)d_in[10];
    const float* mb1   = (const float*)d_in[11];
    const float* mw2   = (const float*)d_in[12];
    const float* mb2   = (const float*)d_in[13];
    const float* modw1 = (const float*)d_in[14];
    const float* modb1 = (const float*)d_in[15];
    const float* modw2 = (const float*)d_in[16];
    const float* modb2 = (const float*)d_in[17];
    const float* nid   = (const float*)d_in[18];
    const int*   conn  = (const int*)d_in[19];
    const int*   bconn = (const int*)d_in[20];
    float* outp = (float*)d_out;

    cudaFuncSetAttribute(cellK2, cudaFuncAttributeMaxDynamicSharedMemorySize, K2_BYTES);
    cudaFuncSetAttribute(cellB_kernel, cudaFuncAttributeMaxDynamicSharedMemorySize, SMEMB_BYTES);

    modk<<<NNN, 256>>>(hin, dlog, prim, trc, modw1, modb1, modw2, modb2, nid);

    cellK2<<<GRID_K2, K2_THREADS, K2_BYTES>>>(
        ccs, hin, pm, sw1, sb1, sw2, sb2, mw1, mb1, mw2, mb2,
        nid, conn, bconn, outp);

    cellB_kernel<<<512, 512, SMEMB_BYTES>>>(conn, trc, outp);
}

// round 11
// speedup vs baseline: 1.0643x; 1.0643x over previous
#include <cuda_runtime.h>
#include <cuda_bf16.h>

#define NNN     16384
#define MODIN   113
#define MODOUT  57

typedef unsigned long long u64;

#define OUT_H    16384
#define OUT_MSG  (OUT_H + 4194304)
#define OUT_HEB  (OUT_MSG + 4194304)

// per (b,n) scratch row of 64: [0:25) sigmoids (16 conn, 8 border, decay@24), [25:57) prim_new
__device__ float g_scr[(size_t)8 * NNN * 64];

__device__ __forceinline__ u64 pk2(float w) {
    u64 r; asm("mov.b64 %0, {%1, %1};" : "=l"(r) : "f"(w)); return r;
}
__device__ __forceinline__ void fma2(u64 &a, u64 b, u64 c) {
    asm("fma.rn.f32x2 %0, %1, %2, %0;" : "+l"(a) : "l"(b), "l"(c));
}
__device__ __forceinline__ void upk2(u64 v, float &lo, float &hi) {
    asm("mov.b64 {%0,%1}, %2;" : "=f"(lo), "=f"(hi) : "l"(v));
}
__device__ __forceinline__ float mytanh(float x) {
    float e = __expf(2.0f * x);
    return 1.0f - __fdividef(2.0f, e + 1.0f);
}
__device__ __forceinline__ float sigm(float x) {
    return __fdividef(1.0f, 1.0f + __expf(-x));
}
__device__ __forceinline__ unsigned smem_u32(const void* p) {
    return (unsigned)__cvta_generic_to_shared(p);
}
__device__ __forceinline__ void cpasync16(unsigned saddr, const void* g) {
    asm volatile("cp.async.cg.shared.global [%0], [%1], 16;" :: "r"(saddr), "l"(g));
}
__device__ __forceinline__ void cp_commit() {
    asm volatile("cp.async.commit_group;");
}
template<int N> __device__ __forceinline__ void cp_wait() {
    asm volatile("cp.async.wait_group %0;" :: "n"(N));
}

// psum-writing partial GEMV; x via LDS.128 broadcast.
// psum slot = 10 floats (8 data + 2 pad): lane stride 40B -> 2-way max on STS.64
__device__ __forceinline__ void gemv_part(const float* __restrict__ W, int iStride,
                                          const float* __restrict__ X,
                                          float* __restrict__ ps,
                                          int kbeg, int kend)
{
    u64 a0 = 0, a1 = 0, a2 = 0, a3 = 0;
    const float* w = W + kbeg * iStride;
    const ulonglong2* x = (const ulonglong2*)(X + kbeg * 8);
#pragma unroll 4
    for (int i = kbeg; i < kend; ++i) {
        u64 wp = pk2(*w); w += iStride;
        ulonglong2 v0 = x[0], v1 = x[1]; x += 2;
        fma2(a0, wp, v0.x); fma2(a1, wp, v0.y);
        fma2(a2, wp, v1.x); fma2(a3, wp, v1.y);
    }
    *(u64*)(ps)     = a0;
    *(u64*)(ps + 2) = a1;
    *(u64*)(ps + 4) = a2;
    *(u64*)(ps + 6) = a3;
}

// full-K GEMV, lane owns ONE output row (8 packed batches)
__device__ __forceinline__ void gemv1(const float* __restrict__ W,
                                      const float* __restrict__ X,
                                      int K, u64* A)
{
    u64 a0 = 0, a1 = 0, a2 = 0, a3 = 0;
    const ulonglong2* x = (const ulonglong2*)X;
#pragma unroll 4
    for (int i = 0; i < K; ++i) {
        u64 wp = pk2(W[i]);
        ulonglong2 v0 = x[0], v1 = x[1]; x += 2;
        fma2(a0, wp, v0.x); fma2(a1, wp, v0.y);
        fma2(a2, wp, v1.x); fma2(a3, wp, v1.y);
    }
    A[0] = a0; A[1] = a1; A[2] = a2; A[3] = a3;
}

// full-K GEMV, lane owns TWO output rows
__device__ __forceinline__ void gemv2(const float* __restrict__ W0,
                                      const float* __restrict__ W1,
                                      const float* __restrict__ X,
                                      int K, u64* A)
{
    u64 a0=0,a1=0,a2=0,a3=0,a4=0,a5=0,a6=0,a7=0;
    const ulonglong2* x = (const ulonglong2*)X;
#pragma unroll 4
    for (int i = 0; i < K; ++i) {
        u64 p0 = pk2(W0[i]), p1 = pk2(W1[i]);
        ulonglong2 v0 = x[0], v1 = x[1]; x += 2;
        fma2(a0, p0, v0.x); fma2(a1, p0, v0.y);
        fma2(a2, p0, v1.x); fma2(a3, p0, v1.y);
        fma2(a4, p1, v0.x); fma2(a5, p1, v0.y);
        fma2(a6, p1, v1.x); fma2(a7, p1, v1.y);
    }
    A[0]=a0; A[1]=a1; A[2]=a2; A[3]=a3;
    A[4]=a4; A[5]=a5; A[6]=a6; A[7]=a7;
}

// tanh(bias + acc) for 8 packed values -> 2 float4 stores
__device__ __forceinline__ void act_store(float* dst, const u64* A, float bias)
{
    float lo, hi; float4 f0, f1;
    upk2(A[0], lo, hi); f0.x = mytanh(bias + lo); f0.y = mytanh(bias + hi);
    upk2(A[1], lo, hi); f0.z = mytanh(bias + lo); f0.w = mytanh(bias + hi);
    upk2(A[2], lo, hi); f1.x = mytanh(bias + lo); f1.y = mytanh(bias + hi);
    upk2(A[3], lo, hi); f1.z = mytanh(bias + lo); f1.w = mytanh(bias + hi);
    ((float4*)dst)[0] = f0; ((float4*)dst)[1] = f1;
}

// =================== K1: per-neuron modulator MLP (256 thr, cp.async) ===================
#define K1_W1  0        // 32 x 113 = 3616
#define K1_W2  3616     // 32 x 57 ([h][o]) = 1824
#define K1_X   5440     // 113 x 8 batch-major = 904
#define K1_H   6344     // 32 x 8 = 256
#define K1_PS  6600     // 256 slots x 10 floats = 2560
#define K1_TOT 9160     // 36640 B

__global__ void __launch_bounds__(256, 5)
modk(const float* __restrict__ hin,  const float* __restrict__ dlog,
     const float* __restrict__ prim, const float* __restrict__ trc,
     const float* __restrict__ modw1, const float* __restrict__ modb1g,
     const float* __restrict__ modw2, const float* __restrict__ modb2g,
     const float* __restrict__ nidg)
{
    __shared__ float s[K1_TOT];
    const int tid = threadIdx.x, wid = tid >> 5, lane = tid & 31;
    const int n = blockIdx.x;

    // ---- cp.async weight staging: group0 = W1, group1 = W2 ----
    {
        unsigned sW1 = smem_u32(s + K1_W1);
        const float4* g1 = (const float4*)(modw1 + (size_t)n * (32*MODIN));
        for (int i = tid; i < 904; i += 256)
            cpasync16(sW1 + i*16, g1 + i);
        cp_commit();
        unsigned sW2 = smem_u32(s + K1_W2);
        const float4* g2 = (const float4*)(modw2 + (size_t)n * (32*MODOUT));
        for (int i = tid; i < 456; i += 256)
            cpasync16(sW2 + i*16, g2 + i);
        cp_commit();
    }

    // ---- build X (warp = batch, lane = d) ----
    {
        int b = wid;
        size_t nb = (size_t)b * NNN + n;
        s[K1_X + (16+lane)*8 + b] = hin[nb*32 + lane];
        s[K1_X + (49+lane)*8 + b] = prim[nb*32 + lane];
        s[K1_X + (81+lane)*8 + b] = nidg[(size_t)n*32 + lane];
        if (lane < 16) s[K1_X + lane*8 + b] = trc[nb*16 + lane];
        if (lane == 0) s[K1_X + 48*8 + b] = dlog[nb];
    }
    cp_wait<1>();          // W1 landed (W2 may still be in flight)
    __syncthreads();

    // ---- layer1: O=32 (lane), K=113 split over 8 warps ----
    {
        int kb = (113*wid) >> 3, ke = (113*(wid+1)) >> 3;
        gemv_part(s + K1_W1 + lane*MODIN, 1, s + K1_X,
                  s + K1_PS + (wid*32 + lane)*10, kb, ke);
    }
    __syncthreads();
    {
        int o = tid >> 3, b = tid & 7;
        float t = modb1g[n*32 + o];
#pragma unroll
        for (int w = 0; w < 8; w++) t += s[K1_PS + (w*32 + o)*10 + b];
        s[K1_H + tid] = mytanh(t);
    }
    cp_wait<0>();          // W2 landed
    __syncthreads();

    // ---- layer2: O=57, K=32; warp = (oh = wid&1, kseg = wid>>1) ----
    {
        int oh = wid & 1, kseg = wid >> 1;
        int o = oh*32 + lane;
        if (oh == 0 || lane < 25)
            gemv_part(s + K1_W2 + o, MODOUT, s + K1_H,
                      s + K1_PS + (wid*32 + lane)*10, kseg*8, kseg*8 + 8);
    }
    __syncthreads();

    // ---- reduce + postprocess + write scratch ----
    for (int v = tid; v < 456; v += 256) {
        int o = v >> 3, b = v & 7;
        int oh = o >> 5, ol = o & 31;
        float t = modb2g[n*57 + o];
#pragma unroll
        for (int ks = 0; ks < 4; ks++)
            t += s[K1_PS + ((oh + 2*ks)*32 + ol)*10 + b];
        float val = (o < 25) ? sigm(t) : (t + s[K1_X + (49 + (o-25))*8 + b]);
        g_scr[((size_t)b*NNN + n)*64 + o] = val;
    }
}

// =================== K2: warp-per-neuron gather + state/msg MLPs ===================
#define OFF_SW1   0        // 64 x 97
#define OFF_SW2   6208     // 32 x 65 pad
#define OFF_MW1   8288     // 64 x 97 (96 used)
#define OFF_MW2   14496    // 32 x 65 pad
#define OFF_SB1   16576
#define OFF_SB2   16640
#define OFF_MB1   16672
#define OFF_MB2   16736
#define WS_BASE   16768
// per-warp workspace (floats): X 97x8 | SG 25x8 | ICON 16i | IBRD 8i | pad | SH 64x8
#define W_SG    776
#define W_ICONI 976     // int index within ws
#define W_IBRDI 992
#define W_SH    1000
#define WSN     1512
#define K2_WARPS 7
#define K2_THREADS (K2_WARPS*32)
#define K2_FLOATS (WS_BASE + K2_WARPS*WSN)
#define K2_BYTES  (K2_FLOATS*4)
#define GRID_K2 296
#define TOT_WARPS (GRID_K2*K2_WARPS)

__global__ void __launch_bounds__(K2_THREADS, 2)
cellK2(const float* __restrict__ ccs, const float* __restrict__ hin,
       const float* __restrict__ pm,
       const float* __restrict__ sw1g, const float* __restrict__ sb1g,
       const float* __restrict__ sw2g, const float* __restrict__ sb2g,
       const float* __restrict__ mw1g, const float* __restrict__ mb1g,
       const float* __restrict__ mw2g, const float* __restrict__ mb2g,
       const float* __restrict__ nidg,
       const int*   __restrict__ conn, const int* __restrict__ bconn,
       float* __restrict__ outp)
{
    extern __shared__ float smf[];
    const int tid  = threadIdx.x;
    const int wid  = tid >> 5;
    const int lane = tid & 31;

    // ---- one-time staging of shared MLP weights ----
    for (int i = tid; i < 1552; i += K2_THREADS)
        ((float4*)(smf + OFF_SW1))[i] = ((const float4*)sw1g)[i];
    for (int i = tid; i < 2048; i += K2_THREADS) {
        int d = i >> 6, h2 = i & 63;
        smf[OFF_SW2 + d*65 + h2] = sw2g[i];
        smf[OFF_MW2 + d*65 + h2] = mw2g[i];
    }
    for (int i = tid; i < 6144; i += K2_THREADS) {
        int hh = i / 96, ii = i - hh*96;
        smf[OFF_MW1 + hh*97 + ii] = mw1g[i];
    }
    if (tid < 64) smf[OFF_SB1 + tid] = sb1g[tid];
    if (tid < 32) smf[OFF_SB2 + tid] = sb2g[tid];
    if (tid >= 64 && tid < 128) smf[OFF_MB1 + tid - 64] = mb1g[tid - 64];
    if (tid >= 32 && tid < 64) smf[OFF_MB2 + tid - 32] = mb2g[tid - 32];
    __syncthreads();

    float* ws = smf + WS_BASE + wid*WSN;
    int*   wi = (int*)ws;

    const int gwarp = blockIdx.x*K2_WARPS + wid;

    for (int n = gwarp; n < NNN; n += TOT_WARPS) {
        const int nc = n >> 8, c = n & 255;
        const bool isb = (c >= 4 && c < 20);

        // ---- P0: loads (X rows: 0-31 h, 64-95 prim_new, 96 decay; SG sigmoids)
        if (lane < 16) wi[W_ICONI + lane] = conn[n*16 + lane];
        if (isb && lane < 8) wi[W_IBRDI + lane] = bconn[(nc*16 + (c-4))*8 + lane];
        float nidv = nidg[(size_t)n*32 + lane];
#pragma unroll
        for (int b = 0; b < 8; b++) {
            size_t nb = (size_t)b * NNN + n;
            ws[lane*8 + b]      = hin[nb*32 + lane];
            ws[(64+lane)*8 + b] = g_scr[nb*64 + 25 + lane];
            if (lane < 25) {
                float sv = g_scr[nb*64 + lane];
                ws[W_SG + lane*8 + b] = sv;
                if (lane == 24) ws[96*8 + b] = sv;
            }
        }
        __syncwarp();

        // ---- P1: gather -> X rows 32-63 (recv)
#pragma unroll
        for (int b = 0; b < 8; b++) {
            size_t bb = (size_t)b * NNN;
            float acc = (c < 4) ? ccs[b*2048 + nc*32 + lane] : 0.0f;
#pragma unroll
            for (int k = 0; k < 16; k++) {
                int ci = wi[W_ICONI + k];
                acc = fmaf(pm[(bb + nc*256 + ci)*32 + lane], ws[W_SG + k*8 + b], acc);
            }
            if (isb) {
#pragma unroll
                for (int k = 0; k < 8; k++) {
                    int bi = wi[W_IBRDI + k];
                    acc = fmaf(pm[(bb + (bi>>4)*256 + 4 + (bi&15))*32 + lane],
                               ws[W_SG + (16+k)*8 + b], acc);
                }
            }
            ws[(32+lane)*8 + b] = acc;
        }
        __syncwarp();

        // ---- P2: state l1 O=64 K=97, lane owns rows lane & lane+32
        {
            u64 A[8];
            gemv2(smf + OFF_SW1 + lane*97, smf + OFF_SW1 + (lane+32)*97, ws, 97, A);
            act_store(ws + W_SH + lane*8,      A,     smf[OFF_SB1 + lane]);
            act_store(ws + W_SH + (lane+32)*8, A + 4, smf[OFF_SB1 + lane + 32]);
        }
        __syncwarp();

        // ---- P3: state l2 O=32 K=64, h_new in place; nid into rows 64-95
        {
            u64 B[4];
            gemv1(smf + OFF_SW2 + lane*65, ws + W_SH, 64, B);
            float dh[8];
            upk2(B[0], dh[0], dh[1]); upk2(B[1], dh[2], dh[3]);
            upk2(B[2], dh[4], dh[5]); upk2(B[3], dh[6], dh[7]);
            float sb = smf[OFF_SB2 + lane];
#pragma unroll
            for (int b = 0; b < 8; b++) {
                float dec = ws[96*8 + b];
                float hv  = ws[lane*8 + b];
                float hn  = dec*hv + (1.0f - dec)*mytanh(dh[b] + sb);
                ws[lane*8 + b] = hn;
                outp[OUT_H + ((size_t)b*NNN + n)*32 + lane] = hn;
            }
            float4 nf = make_float4(nidv, nidv, nidv, nidv);
            ((float4*)(ws + (64+lane)*8))[0] = nf;
            ((float4*)(ws + (64+lane)*8))[1] = nf;
        }
        __syncwarp();

        // ---- P4: msg l1 O=64 K=96 (X rows: h_new | recv | nid)
        {
            u64 A[8];
            gemv2(smf + OFF_MW1 + lane*97, smf + OFF_MW1 + (lane+32)*97, ws, 96, A);
            act_store(ws + W_SH + lane*8,      A,     smf[OFF_MB1 + lane]);
            act_store(ws + W_SH + (lane+32)*8, A + 4, smf[OFF_MB1 + lane + 32]);
        }
        __syncwarp();

        // ---- P5: msg l2 O=32 K=64 -> STG msg
        {
            u64 B[4];
            gemv1(smf + OFF_MW2 + lane*65, ws + W_SH, 64, B);
            float dm[8];
            upk2(B[0], dm[0], dm[1]); upk2(B[1], dm[2], dm[3]);
            upk2(B[2], dm[4], dm[5]); upk2(B[3], dm[6], dm[7]);
            float mb = smf[OFF_MB2 + lane];
#pragma unroll
            for (int b = 0; b < 8; b++)
                outp[OUT_MSG + ((size_t)b*NNN + n)*32 + lane] = mytanh(dm[b] + mb);
        }
        __syncwarp();
    }
}

// ---------------- kernel B: hebbian + readout (2 threads per neuron) ----------------
#define SMEMB_BYTES (8448*4 + 4096*4)

__global__ void __launch_bounds__(512, 2)
cellB_kernel(const int* __restrict__ conn,
             const float* __restrict__ trc,
             float* __restrict__ outp)
{
    extern __shared__ float smb[];
    float* ms = smb;                    // 256 x 33
    int*   cs = (int*)(smb + 8448);     // 4096
    const int b  = blockIdx.x >> 6;
    const int nc = blockIdx.x & 63;
    const int tid = threadIdx.x;

    const float* msgg = outp + OUT_MSG + ((size_t)b*NNN + nc*256) * 32;
    for (int i = tid; i < 8192; i += 512)
        ms[(i >> 5)*33 + (i & 31)] = msgg[i];
    const int4* cg = (const int4*)(conn + nc*4096);
    for (int i = tid; i < 1024; i += 512) ((int4*)cs)[i] = cg[i];
    __syncthreads();

    const int c  = tid >> 1;
    const int kh = tid & 1;
    float me[32];
#pragma unroll
    for (int d = 0; d < 32; d++) me[d] = ms[c*33 + d];

    const size_t base = (size_t)b*NNN + nc*256 + c;
    float4 t4[2];
    t4[0] = ((const float4*)(trc + base*16 + kh*8))[0];
    t4[1] = ((const float4*)(trc + base*16 + kh*8))[1];

    float heb[8];
#pragma unroll
    for (int k = 0; k < 8; k++) {
        int ci = cs[c*16 + kh*8 + k];
        const float* nb = &ms[ci*33];
        float a0 = 0.0f, a1 = 0.0f;
#pragma unroll
        for (int d = 0; d < 32; d += 2) {
            a0 = fmaf(me[d],   nb[d],   a0);
            a1 = fmaf(me[d+1], nb[d+1], a1);
        }
        heb[k] = (a0 + a1) * 0.003125f;
    }
    float4* h4 = (float4*)(outp + OUT_HEB + base*16 + kh*8);
    h4[0] = make_float4(fmaf(0.9f,t4[0].x,heb[0]), fmaf(0.9f,t4[0].y,heb[1]),
                        fmaf(0.9f,t4[0].z,heb[2]), fmaf(0.9f,t4[0].w,heb[3]));
    h4[1] = make_float4(fmaf(0.9f,t4[1].x,heb[4]), fmaf(0.9f,t4[1].y,heb[5]),
                        fmaf(0.9f,t4[1].z,heb[6]), fmaf(0.9f,t4[1].w,heb[7]));

    if (tid < 32) {
        float r = 0.25f * (ms[252*33 + tid] + ms[253*33 + tid] +
                           ms[254*33 + tid] + ms[255*33 + tid]);
        outp[b*2048 + nc*32 + tid] = r;
    }
}

extern "C" void kernel_launch(void* const* d_in, const int* in_sizes, int n_in,
                              void* d_out, int out_size)
{
    const float* ccs   = (const float*)d_in[0];
    const float* hin   = (const float*)d_in[1];
    const float* pm    = (const float*)d_in[2];
    const float* dlog  = (const float*)d_in[3];
    const float* prim  = (const float*)d_in[4];
    const float* trc   = (const float*)d_in[5];
    const float* sw1   = (const float*)d_in[6];
    const float* sb1   = (const float*)d_in[7];
    const float* sw2   = (const float*)d_in[8];
    const float* sb2   = (const float*)d_in[9];
    const float* mw1   = (const float*)d_in[10];
    const float* mb1   = (const float*)d_in[11];
    const float* mw2   = (const float*)d_in[12];
    const float* mb2   = (const float*)d_in[13];
    const float* modw1 = (const float*)d_in[14];
    const float* modb1 = (const float*)d_in[15];
    const float* modw2 = (const float*)d_in[16];
    const float* modb2 = (const float*)d_in[17];
    const float* nid   = (const float*)d_in[18];
    const int*   conn  = (const int*)d_in[19];
    const int*   bconn = (const int*)d_in[20];
    float* outp = (float*)d_out;

    cudaFuncSetAttribute(cellK2, cudaFuncAttributeMaxDynamicSharedMemorySize, K2_BYTES);
    cudaFuncSetAttribute(cellB_kernel, cudaFuncAttributeMaxDynamicSharedMemorySize, SMEMB_BYTES);

    modk<<<NNN, 256>>>(hin, dlog, prim, trc, modw1, modb1, modw2, modb2, nid);

    cellK2<<<GRID_K2, K2_THREADS, K2_BYTES>>>(
        ccs, hin, pm, sw1, sb1, sw2, sb2, mw1, mb1, mw2, mb2,
        nid, conn, bconn, outp);

    cellB_kernel<<<512, 512, SMEMB_BYTES>>>(conn, trc, outp);
}